// round 5
// baseline (speedup 1.0000x reference)
#include <cuda_runtime.h>
#include <cuda_bf16.h>
#include <cstdint>

// Problem constants
#define T_SEQ 512
#define B_SZ  64
#define E_SZ  512
#define G3E   1536
#define M_ROWS (T_SEQ * B_SZ)      // 32768

// ---------------- device scratch ----------------
__device__ float g_x[T_SEQ * B_SZ * E_SZ];
__device__ float g_xproj[T_SEQ * B_SZ * G3E];
__device__ float g_h[B_SZ * E_SZ];
__device__ unsigned g_bar[8];          // per-batch-group recurrence barrier counters
__device__ unsigned g_prog[M_ROWS / 128];   // 256 per-mblock GEMM progress counters
__device__ unsigned g_ticket[2];       // per-layer GEMM tile tickets

// ---------------- f32x2 helpers ----------------
__device__ __forceinline__ void fma2(unsigned long long& d, unsigned long long a,
                                     unsigned long long b) {
    asm("fma.rn.f32x2 %0, %1, %2, %3;" : "=l"(d) : "l"(a), "l"(b), "l"(d));
}
__device__ __forceinline__ float f32x2_sum(unsigned long long v) {
    return __uint_as_float((unsigned)v) + __uint_as_float((unsigned)(v >> 32));
}
__device__ __forceinline__ unsigned long long dup2(float x) {
    unsigned long long r; unsigned u = __float_as_uint(x);
    asm("mov.b64 %0, {%1, %1};" : "=l"(r) : "r"(u));
    return r;
}

// ---------------- release/acquire counter primitives ----------------
__device__ __forceinline__ void ctr_release_add(unsigned* ctr) {
    asm volatile("red.release.gpu.global.add.u32 [%0], %1;" :: "l"(ctr), "r"(1u) : "memory");
}
__device__ __forceinline__ void ctr_wait(unsigned* ctr, unsigned target) {
    unsigned cur;
    do {
        asm volatile("ld.acquire.gpu.u32 %0, [%1];" : "=r"(cur) : "l"(ctr) : "memory");
    } while ((int)(cur - target) < 0);
}

// ---------------- embedding gather (+ counter reset) ----------------
__global__ void embed_kernel(const int* __restrict__ idx,
                             const float* __restrict__ emb,
                             float* __restrict__ out) {
    if (blockIdx.x == 0) {
        if (threadIdx.x < 256) g_prog[threadIdx.x] = 0u;
        if (threadIdx.x < 8)   g_bar[threadIdx.x] = 0u;
        if (threadIdx.x < 2)   g_ticket[threadIdx.x] = 0u;
    }
    int i = blockIdx.x * blockDim.x + threadIdx.x;
    const int total = T_SEQ * B_SZ * (E_SZ / 4);
    if (i >= total) return;
    int row = i >> 7;
    int col = i & 127;
    int tok = idx[row];
    reinterpret_cast<float4*>(out)[i] =
        reinterpret_cast<const float4*>(emb)[(size_t)tok * 128 + col];
}

// ---------------- persistent ticket GEMM ----------------
// C[M,G3E] = A[M,512] * B[G3E,512]^T + bias. 128x128 tile, BK=8, 256 thr, 8x8 micro.
// grid = 148 (one CTA per SM), tiles taken in ascending (mblock, nblock) ticket order.
// After each finished tile: release-increment g_prog[mblock] (12 => mblock complete).
#define BM 128
#define BN 128
#define GBK 8
#define MB_TILES (G3E / BN)                 // 12
#define NTILES ((M_ROWS / BM) * MB_TILES)   // 3072

__global__ __launch_bounds__(256, 2) void gemm_persist(
    const float* __restrict__ A, const float* __restrict__ Bm,
    const float* __restrict__ bias, float* __restrict__ C, int layer) {
    __shared__ float As[GBK][BM];
    __shared__ float Bs[GBK][BN];
    __shared__ int s_tile;

    const int tid = threadIdx.x;
    const int tx = tid & 15;
    const int ty = tid >> 4;
    const int lrow = tid >> 1;          // 0..127
    const int lkq = (tid & 1) << 2;     // 0 or 4

    for (;;) {
        if (tid == 0) s_tile = (int)atomicAdd(&g_ticket[layer], 1u);
        __syncthreads();
        int tile = s_tile;
        if (tile >= NTILES) break;

        const int mb = tile / MB_TILES;
        const int nb = tile - mb * MB_TILES;
        const int bm = mb * BM;
        const int bn = nb * BN;

        unsigned long long acc2[4][8];
#pragma unroll
        for (int i = 0; i < 4; i++)
#pragma unroll
            for (int j = 0; j < 8; j++) acc2[i][j] = 0ULL;

        float4 va = *reinterpret_cast<const float4*>(&A[(size_t)(bm + lrow) * E_SZ + lkq]);
        float4 vb = *reinterpret_cast<const float4*>(&Bm[(size_t)(bn + lrow) * E_SZ + lkq]);

        for (int k0 = 0; k0 < E_SZ; k0 += GBK) {
            As[lkq + 0][lrow] = va.x; As[lkq + 1][lrow] = va.y;
            As[lkq + 2][lrow] = va.z; As[lkq + 3][lrow] = va.w;
            Bs[lkq + 0][lrow] = vb.x; Bs[lkq + 1][lrow] = vb.y;
            Bs[lkq + 2][lrow] = vb.z; Bs[lkq + 3][lrow] = vb.w;
            __syncthreads();

            if (k0 + GBK < E_SZ) {
                va = *reinterpret_cast<const float4*>(&A[(size_t)(bm + lrow) * E_SZ + k0 + GBK + lkq]);
                vb = *reinterpret_cast<const float4*>(&Bm[(size_t)(bn + lrow) * E_SZ + k0 + GBK + lkq]);
            }

#pragma unroll
            for (int k = 0; k < GBK; k++) {
                ulonglong2 aq0 = *reinterpret_cast<const ulonglong2*>(&As[k][ty * 8]);
                ulonglong2 aq1 = *reinterpret_cast<const ulonglong2*>(&As[k][ty * 8 + 4]);
                float4 b0 = *reinterpret_cast<const float4*>(&Bs[k][tx * 8]);
                float4 b1 = *reinterpret_cast<const float4*>(&Bs[k][tx * 8 + 4]);
                unsigned long long ap[4] = {aq0.x, aq0.y, aq1.x, aq1.y};
                unsigned long long bd[8] = {dup2(b0.x), dup2(b0.y), dup2(b0.z), dup2(b0.w),
                                            dup2(b1.x), dup2(b1.y), dup2(b1.z), dup2(b1.w)};
#pragma unroll
                for (int ip = 0; ip < 4; ip++)
#pragma unroll
                    for (int j = 0; j < 8; j++) fma2(acc2[ip][j], ap[ip], bd[j]);
            }
            __syncthreads();
        }

        float bv[8];
        {
            float4 bias0 = *reinterpret_cast<const float4*>(&bias[bn + tx * 8]);
            float4 bias1 = *reinterpret_cast<const float4*>(&bias[bn + tx * 8 + 4]);
            bv[0] = bias0.x; bv[1] = bias0.y; bv[2] = bias0.z; bv[3] = bias0.w;
            bv[4] = bias1.x; bv[5] = bias1.y; bv[6] = bias1.z; bv[7] = bias1.w;
        }
#pragma unroll
        for (int ip = 0; ip < 4; ip++) {
            float lo[8], hi[8];
#pragma unroll
            for (int j = 0; j < 8; j++) {
                lo[j] = __uint_as_float((unsigned)acc2[ip][j]) + bv[j];
                hi[j] = __uint_as_float((unsigned)(acc2[ip][j] >> 32)) + bv[j];
            }
            int row0 = bm + ty * 8 + 2 * ip;
            float* cp0 = &C[(size_t)row0 * G3E + bn + tx * 8];
            float* cp1 = cp0 + G3E;
            *reinterpret_cast<float4*>(cp0)     = make_float4(lo[0], lo[1], lo[2], lo[3]);
            *reinterpret_cast<float4*>(cp0 + 4) = make_float4(lo[4], lo[5], lo[6], lo[7]);
            *reinterpret_cast<float4*>(cp1)     = make_float4(hi[0], hi[1], hi[2], hi[3]);
            *reinterpret_cast<float4*>(cp1 + 4) = make_float4(hi[4], hi[5], hi[6], hi[7]);
        }

        __syncthreads();                       // all STGs issued before the publish
        if (tid == 0) ctr_release_add(&g_prog[mb]);
    }
}

// ---------------- persistent GRU recurrence ----------------
// 128 CTAs = 8 bg x 16 eg, 256 threads. Per-bg barriers. Polls GEMM progress
// (g_prog[mb] >= gtarget) before consuming xproj of each new mblock (2 steps).
// Two-round partial reduce: union smem region = max(8x512 h, 4x768 partials) = 4096 floats.
#define RGRID 128
#define EGROUPS 16
#define BTILE 8
#define ESLICE 32
#define WROWS 96
#define WSTR 516
#define REGION_FLOATS 4096
#define RSMEM_FLOATS (WROWS * WSTR + REGION_FLOATS)
#define RSMEM_BYTES (RSMEM_FLOATS * 4)         // 214,528 B

__global__ __launch_bounds__(256, 2) void gru_recur_kernel(
    const float* __restrict__ xproj,
    const float* __restrict__ Whh,
    const float* __restrict__ bhh,
    const int* __restrict__ lens,
    float* __restrict__ hbuf,
    float* __restrict__ ybuf,
    float* __restrict__ finals,
    int epoch, unsigned gtarget)
{
    extern __shared__ float smem[];
    float* sh_w = smem;                        // WROWS * WSTR
    float* sh_h = smem + WROWS * WSTR;         // 8*512 floats (dot phase)
    float* sh_part = sh_h;                     // 4*768 floats (reduce rounds, overlapped)

    const int tid = threadIdx.x;
    const int cta = blockIdx.x;
    const int bg = cta / EGROUPS;
    const int eg = cta % EGROUPS;
    const int ebase = eg * ESLICE;
    const int w = tid >> 5;
    const int jg = tid & 31;
    const int bR = w;
    const int bglob = bg * BTILE + bR;
    const int e = ebase + jg;
    const int kbase = w * 64;
    unsigned* ctr = &g_bar[bg];
    const unsigned tbase = (unsigned)epoch * (16u * (T_SEQ + 1)) + 16u;

    // weight cache: row j = elocal*3 + gate, stride WSTR (conflict-free LDS.128)
    for (int idx = tid; idx < WROWS * (E_SZ / 4); idx += 256) {
        int j = idx >> 7;
        int kq = (idx & 127) << 2;
        int el = j / 3, gate = j - el * 3;
        *reinterpret_cast<float4*>(&sh_w[j * WSTR + kq]) =
            *reinterpret_cast<const float4*>(&Whh[(size_t)(gate * E_SZ + ebase + el) * E_SZ + kq]);
    }

    const float bh0 = bhh[0 * E_SZ + e];
    const float bh1 = bhh[1 * E_SZ + e];
    const float bh2 = bhh[2 * E_SZ + e];
    const int mylen = lens[bglob];

    hbuf[bglob * E_SZ + e] = 0.f;
    __syncthreads();
    if (tid == 0) ctr_release_add(ctr);
    if (tid == 0) {
        ctr_wait(&g_prog[0], gtarget);        // xproj mblock 0 (steps 0,1) ready
        ctr_wait(ctr, tbase);
    }
    __syncthreads();

    const float* wp0 = sh_w + (jg * 3 + 0) * WSTR;
    const float* wp1 = wp0 + WSTR;
    const float* wp2 = wp1 + WSTR;

    float hnew = 0.f;

    for (int t = 0; t < T_SEQ; t++) {
        // stage h tile + load xp[t]
        {
            const float4* hsrc = reinterpret_cast<const float4*>(hbuf + bg * BTILE * E_SZ);
            float4* hdst = reinterpret_cast<float4*>(sh_h);
#pragma unroll
            for (int i = 0; i < 4; i++) hdst[tid + i * 256] = hsrc[tid + i * 256];
        }
        const float* xp = xproj + ((size_t)t * B_SZ + bglob) * G3E;
        float xr = xp[e];
        float xz = xp[E_SZ + e];
        float xn = xp[2 * E_SZ + e];
        __syncthreads();

        float hprev = sh_h[bR * E_SZ + e];

        // dot phase
        unsigned long long a0[8], a1[8], a2[8];
#pragma unroll
        for (int b = 0; b < 8; b++) { a0[b] = 0ULL; a1[b] = 0ULL; a2[b] = 0ULL; }

#pragma unroll 4
        for (int kk = 0; kk < 16; kk++) {
            int k4 = kbase + kk * 4;
            ulonglong2 w0 = *reinterpret_cast<const ulonglong2*>(wp0 + k4);
            ulonglong2 w1 = *reinterpret_cast<const ulonglong2*>(wp1 + k4);
            ulonglong2 w2 = *reinterpret_cast<const ulonglong2*>(wp2 + k4);
#pragma unroll
            for (int b = 0; b < 8; b++) {
                ulonglong2 h2 = *reinterpret_cast<const ulonglong2*>(sh_h + b * E_SZ + k4);
                fma2(a0[b], h2.x, w0.x); fma2(a0[b], h2.y, w0.y);
                fma2(a1[b], h2.x, w1.x); fma2(a1[b], h2.y, w1.y);
                fma2(a2[b], h2.x, w2.x); fma2(a2[b], h2.y, w2.y);
            }
        }
        __syncthreads();          // sh_h reads done

        // two-round partial store + reduce (region = 4096 floats)
        float s0 = 0.f, s1 = 0.f, s2 = 0.f;
#pragma unroll
        for (int rnd = 0; rnd < 2; rnd++) {
            if ((w >> 2) == rnd) {
                float* pw = sh_part + (w & 3) * (3 * BTILE * ESLICE);
#pragma unroll
                for (int b = 0; b < 8; b++) {
                    pw[(0 * BTILE + b) * ESLICE + jg] = f32x2_sum(a0[b]);
                    pw[(1 * BTILE + b) * ESLICE + jg] = f32x2_sum(a1[b]);
                    pw[(2 * BTILE + b) * ESLICE + jg] = f32x2_sum(a2[b]);
                }
            }
            __syncthreads();
#pragma unroll
            for (int ww = 0; ww < 4; ww++) {
                const float* pw = sh_part + ww * (3 * BTILE * ESLICE);
                s0 += pw[(0 * BTILE + bR) * ESLICE + jg];
                s1 += pw[(1 * BTILE + bR) * ESLICE + jg];
                s2 += pw[(2 * BTILE + bR) * ESLICE + jg];
            }
            __syncthreads();
        }

        float hr = s0 + bh0, hz = s1 + bh1, hn = s2 + bh2;
        float r = 1.f / (1.f + expf(-(xr + hr)));
        float z = 1.f / (1.f + expf(-(xz + hz)));
        float n = tanhf(xn + r * hn);
        bool m = (t < mylen);
        hnew = m ? ((1.f - z) * n + z * hprev) : hprev;

        hbuf[bglob * E_SZ + e] = hnew;
        __syncthreads();
        if (tid == 0) ctr_release_add(ctr);

        ybuf[((size_t)t * B_SZ + bglob) * E_SZ + e] = m ? hnew : 0.f;

        if (tid == 0) {
            if ((t & 1) && (t + 1 < T_SEQ))
                ctr_wait(&g_prog[(t + 1) >> 1], gtarget);   // next xproj mblock
            ctr_wait(ctr, tbase + 16u * (t + 1));
        }
        __syncthreads();
    }

    finals[bglob * E_SZ + e] = hnew;
}

// ---------------- launch: forked-stream producer/consumer pipeline ----------------
extern "C" void kernel_launch(void* const* d_in, const int* in_sizes, int n_in,
                              void* d_out, int out_size) {
    const int*   input_batch = (const int*)d_in[0];
    const int*   lens        = (const int*)d_in[1];
    const float* emb         = (const float*)d_in[2];
    const float* W_ih        = (const float*)d_in[3];
    const float* W_hh        = (const float*)d_in[4];
    const float* b_ih        = (const float*)d_in[5];
    const float* b_hh        = (const float*)d_in[6];
    float* out = (float*)d_out;

    void* p;
    cudaGetSymbolAddress(&p, g_x);     float* gx  = (float*)p;
    cudaGetSymbolAddress(&p, g_xproj); float* gxp = (float*)p;
    cudaGetSymbolAddress(&p, g_h);     float* gh  = (float*)p;

    cudaFuncSetAttribute(gru_recur_kernel,
                         cudaFuncAttributeMaxDynamicSharedMemorySize, RSMEM_BYTES);

    const size_t out_x_elems = (size_t)T_SEQ * B_SZ * E_SZ;
    float* finals0 = out + out_x_elems;
    float* finals1 = out + out_x_elems + B_SZ * E_SZ;

    cudaStream_t s2;
    cudaStreamCreateWithFlags(&s2, cudaStreamNonBlocking);
    cudaEvent_t evE, evR0, evG1;
    cudaEventCreateWithFlags(&evE,  cudaEventDisableTiming);
    cudaEventCreateWithFlags(&evR0, cudaEventDisableTiming);
    cudaEventCreateWithFlags(&evG1, cudaEventDisableTiming);

    // embeddings + counter reset (default stream)
    {
        int total = T_SEQ * B_SZ * (E_SZ / 4);
        embed_kernel<<<(total + 255) / 256, 256>>>(input_batch, emb, gx);
    }
    cudaEventRecord(evE, 0);
    cudaStreamWaitEvent(s2, evE, 0);

    // layer 0: GEMM producer on s2, recurrence consumer on default stream
    gemm_persist<<<148, 256, 0, s2>>>(gx, W_ih, b_ih, gxp, 0);
    gru_recur_kernel<<<RGRID, 256, RSMEM_BYTES>>>(gxp, W_hh, b_hh, lens, gh, gx,
                                                  finals0, 0, 12u);
    cudaEventRecord(evR0, 0);
    cudaStreamWaitEvent(s2, evR0, 0);

    // layer 1: GEMM (reads layer-0 outputs) on s2, recurrence on default stream
    gemm_persist<<<148, 256, 0, s2>>>(gx, W_ih + (size_t)G3E * E_SZ,
                                      b_ih + G3E, gxp, 1);
    gru_recur_kernel<<<RGRID, 256, RSMEM_BYTES>>>(gxp, W_hh + (size_t)G3E * E_SZ,
                                                  b_hh + G3E, lens, gh, out,
                                                  finals1, 1, 24u);
    // join the producer branch
    cudaEventRecord(evG1, s2);
    cudaStreamWaitEvent(0, evG1, 0);

    // destroy only when not capturing (a capturing stream must not be destroyed)
    cudaStreamCaptureStatus cst = cudaStreamCaptureStatusNone;
    cudaError_t qerr = cudaStreamIsCapturing(s2, &cst);
    if (qerr != cudaSuccess) { cudaGetLastError(); cst = cudaStreamCaptureStatusActive; }
    if (cst == cudaStreamCaptureStatusNone) {
        cudaEventDestroy(evE);
        cudaEventDestroy(evR0);
        cudaEventDestroy(evG1);
        cudaStreamDestroy(s2);
    }
}

// round 6
// speedup vs baseline: 1.0700x; 1.0700x over previous
#include <cuda_runtime.h>
#include <cuda_bf16.h>
#include <cstdint>

// Problem constants
#define T_SEQ 512
#define B_SZ  64
#define E_SZ  512
#define G3E   1536
#define M_ROWS (T_SEQ * B_SZ)

// ---------------- device scratch ----------------
__device__ float g_x[T_SEQ * B_SZ * E_SZ];
__device__ float g_xproj[T_SEQ * B_SZ * G3E];
__device__ float g_h[B_SZ * E_SZ];
__device__ unsigned g_step[128];     // per-(bg,eg) monotonic progress counters

// ---------------- f32x2 helpers ----------------
__device__ __forceinline__ void fma2(unsigned long long& d, unsigned long long a,
                                     unsigned long long b) {
    asm("fma.rn.f32x2 %0, %1, %2, %3;" : "=l"(d) : "l"(a), "l"(b), "l"(d));
}
__device__ __forceinline__ float f32x2_sum(unsigned long long v) {
    return __uint_as_float((unsigned)v) + __uint_as_float((unsigned)(v >> 32));
}
__device__ __forceinline__ unsigned long long dup2(float x) {
    unsigned long long r; unsigned u = __float_as_uint(x);
    asm("mov.b64 %0, {%1, %1};" : "=l"(r) : "r"(u));
    return r;
}

// ---------------- release/acquire counter primitives ----------------
__device__ __forceinline__ void ctr_release_add(unsigned* ctr) {
    asm volatile("red.release.gpu.global.add.u32 [%0], %1;" :: "l"(ctr), "r"(1u) : "memory");
}
__device__ __forceinline__ void ctr_wait(unsigned* ctr, unsigned target) {
    unsigned cur;
    do {
        asm volatile("ld.acquire.gpu.u32 %0, [%1];" : "=r"(cur) : "l"(ctr) : "memory");
    } while ((int)(cur - target) < 0);
}

// ---------------- embedding gather (+ counter reset) ----------------
__global__ void embed_kernel(const int* __restrict__ idx,
                             const float* __restrict__ emb,
                             float* __restrict__ out) {
    if (blockIdx.x == 0 && threadIdx.x < 128) g_step[threadIdx.x] = 0u;
    int i = blockIdx.x * blockDim.x + threadIdx.x;
    const int total = T_SEQ * B_SZ * (E_SZ / 4);
    if (i >= total) return;
    int row = i >> 7;
    int col = i & 127;
    int tok = idx[row];
    reinterpret_cast<float4*>(out)[i] =
        reinterpret_cast<const float4*>(emb)[(size_t)tok * 128 + col];
}

// ---------------- fp32 GEMM (R2 version: 2 CTAs/SM) ----------------
#define BM 128
#define BN 128
#define BK 16

__global__ __launch_bounds__(256) void gemm_nt_bias(
    const float* __restrict__ A, const float* __restrict__ Bm,
    const float* __restrict__ bias, float* __restrict__ C,
    int M, int N, int K) {
    __shared__ float As[BK][BM];
    __shared__ float Bs[BK][BN];

    const int tid = threadIdx.x;
    const int bm = blockIdx.y * BM;
    const int bn = blockIdx.x * BN;
    const int tx = tid & 15;
    const int ty = tid >> 4;

    unsigned long long acc2[4][8];
#pragma unroll
    for (int i = 0; i < 4; i++)
#pragma unroll
        for (int j = 0; j < 8; j++) acc2[i][j] = 0ULL;

    for (int k0 = 0; k0 < K; k0 += BK) {
#pragma unroll
        for (int it = 0; it < 2; it++) {
            int f = tid + it * 256;
            int row = f >> 2;
            int kq = (f & 3) << 2;
            float4 va = *reinterpret_cast<const float4*>(&A[(size_t)(bm + row) * K + k0 + kq]);
            As[kq + 0][row] = va.x; As[kq + 1][row] = va.y;
            As[kq + 2][row] = va.z; As[kq + 3][row] = va.w;
            float4 vb = *reinterpret_cast<const float4*>(&Bm[(size_t)(bn + row) * K + k0 + kq]);
            Bs[kq + 0][row] = vb.x; Bs[kq + 1][row] = vb.y;
            Bs[kq + 2][row] = vb.z; Bs[kq + 3][row] = vb.w;
        }
        __syncthreads();

#pragma unroll
        for (int k = 0; k < BK; k++) {
            ulonglong2 aq0 = *reinterpret_cast<const ulonglong2*>(&As[k][ty * 8]);
            ulonglong2 aq1 = *reinterpret_cast<const ulonglong2*>(&As[k][ty * 8 + 4]);
            float4 b0 = *reinterpret_cast<const float4*>(&Bs[k][tx * 8]);
            float4 b1 = *reinterpret_cast<const float4*>(&Bs[k][tx * 8 + 4]);
            unsigned long long ap[4] = {aq0.x, aq0.y, aq1.x, aq1.y};
            unsigned long long bd[8] = {dup2(b0.x), dup2(b0.y), dup2(b0.z), dup2(b0.w),
                                        dup2(b1.x), dup2(b1.y), dup2(b1.z), dup2(b1.w)};
#pragma unroll
            for (int ip = 0; ip < 4; ip++)
#pragma unroll
                for (int j = 0; j < 8; j++) fma2(acc2[ip][j], ap[ip], bd[j]);
        }
        __syncthreads();
    }

    float bv[8];
    {
        float4 bias0 = *reinterpret_cast<const float4*>(&bias[bn + tx * 8]);
        float4 bias1 = *reinterpret_cast<const float4*>(&bias[bn + tx * 8 + 4]);
        bv[0] = bias0.x; bv[1] = bias0.y; bv[2] = bias0.z; bv[3] = bias0.w;
        bv[4] = bias1.x; bv[5] = bias1.y; bv[6] = bias1.z; bv[7] = bias1.w;
    }
#pragma unroll
    for (int ip = 0; ip < 4; ip++) {
        float lo[8], hi[8];
#pragma unroll
        for (int j = 0; j < 8; j++) {
            lo[j] = __uint_as_float((unsigned)acc2[ip][j]) + bv[j];
            hi[j] = __uint_as_float((unsigned)(acc2[ip][j] >> 32)) + bv[j];
        }
        int row0 = bm + ty * 8 + 2 * ip;
        float* cp0 = &C[(size_t)row0 * N + bn + tx * 8];
        float* cp1 = cp0 + N;
        *reinterpret_cast<float4*>(cp0)     = make_float4(lo[0], lo[1], lo[2], lo[3]);
        *reinterpret_cast<float4*>(cp0 + 4) = make_float4(lo[4], lo[5], lo[6], lo[7]);
        *reinterpret_cast<float4*>(cp1)     = make_float4(hi[0], hi[1], hi[2], hi[3]);
        *reinterpret_cast<float4*>(cp1 + 4) = make_float4(hi[4], hi[5], hi[6], hi[7]);
    }
}

// ---------------- persistent GRU recurrence, fine-grained sync ----------------
// 128 CTAs = 8 bg x 16 eg, 256 threads = 8 warps.
// Per-(bg,eg) progress counters: CTA eg publishes its 32-col hnew slice, then
// release-adds g_step[bg*16+eg]. Warp w (k-slice [64w,64w+64)) of every CTA in
// the bg waits only on its two producer counters (eg = 2w, 2w+1), stages its
// own 8x64 h slice into a private smem stripe, and runs its dot — no CTA-wide
// head-of-step barrier. hprev lives in a register (mapping is step-invariant).
// Cross-warp reduce in two rounds through a buffer overlapping the (dead) h region.
#define RGRID 128
#define EGROUPS 16
#define BTILE 8
#define WROWS 96
#define WSTR 516
#define HS_FLOATS (8 * 512)                 // 8 warp stripes x (8 rows x 64 cols)
#define PART_FLOATS (4 * 3 * BTILE * 32)    // 3072 (one round: 4 warps)
#define REGION_FLOATS (HS_FLOATS)           // partials overlap dead h region (3072<=4096)
#define RSMEM_FLOATS (WROWS * WSTR + REGION_FLOATS)
#define RSMEM_BYTES (RSMEM_FLOATS * 4)      // 214,528 B

__global__ __launch_bounds__(256, 1) void gru_recur_kernel(
    const float* __restrict__ xproj,
    const float* __restrict__ Whh,
    const float* __restrict__ bhh,
    const int* __restrict__ lens,
    float* __restrict__ hbuf,
    float* __restrict__ ybuf,
    float* __restrict__ finals,
    int epoch)
{
    extern __shared__ float smem[];
    float* sh_w = smem;                          // WROWS * WSTR
    float* sh_h = smem + WROWS * WSTR;           // 8 stripes of 512 floats
    float* sh_part = sh_h;                       // 3072-float reduce buffer (overlap)

    const int tid = threadIdx.x;
    const int cta = blockIdx.x;
    const int bg = cta / EGROUPS;
    const int eg = cta % EGROUPS;
    const int ebase = eg * 32;
    const int w = tid >> 5;              // warp id: k-slice AND reduce-phase batch row
    const int jg = tid & 31;
    const int bglob = bg * BTILE + w;
    const int e = ebase + jg;
    const int kbase = w * 64;

    unsigned* my_ctr = &g_step[cta];
    unsigned* p0 = &g_step[bg * EGROUPS + 2 * w];
    unsigned* p1 = p0 + 1;
    const unsigned tgt0 = (unsigned)epoch * (T_SEQ + 1) + 1u;   // value after init-publish

    // weight cache: row j = elocal*3 + gate, stride WSTR (conflict-free LDS.128)
    for (int idx = tid; idx < WROWS * (E_SZ / 4); idx += 256) {
        int j = idx >> 7;
        int kq = (idx & 127) << 2;
        int el = j / 3, gate = j - el * 3;
        *reinterpret_cast<float4*>(&sh_w[j * WSTR + kq]) =
            *reinterpret_cast<const float4*>(&Whh[(size_t)(gate * E_SZ + ebase + el) * E_SZ + kq]);
    }

    const float bh0 = bhh[0 * E_SZ + e];
    const float bh1 = bhh[1 * E_SZ + e];
    const float bh2 = bhh[2 * E_SZ + e];
    const int mylen = lens[bglob];

    // init: zero our slice of h, publish
    hbuf[bglob * E_SZ + e] = 0.f;
    __syncthreads();
    if (tid == 0) ctr_release_add(my_ctr);

    const float* wp0 = sh_w + (jg * 3 + 0) * WSTR;
    const float* wp1 = wp0 + WSTR;
    const float* wp2 = wp1 + WSTR;
    float* sh_hs = sh_h + w * 512;               // this warp's stripe: [b][64]

    float hprev = 0.f;
    float hnew = 0.f;

    for (int t = 0; t < T_SEQ; t++) {
        // xp prefetch (independent of h)
        const float* xp = xproj + ((size_t)t * B_SZ + bglob) * G3E;
        float xr = xp[e];
        float xz = xp[E_SZ + e];
        float xn = xp[2 * E_SZ + e];

        // wait for this warp's two producer CTAs (all lanes poll; own acquire
        // orders each lane's subsequent loads)
        ctr_wait(p0, tgt0 + (unsigned)t);
        ctr_wait(p1, tgt0 + (unsigned)t);

        // stage this warp's 8x64 h slice: 4 float4 per lane
        {
            const float4* hb4 = reinterpret_cast<const float4*>(hbuf);
#pragma unroll
            for (int i = 0; i < 4; i++) {
                int f = jg + i * 32;             // 0..127
                int b = f >> 4, c4 = f & 15;
                float4 v = hb4[(bg * BTILE + b) * 128 + 16 * w + c4];
                *reinterpret_cast<float4*>(&sh_hs[b * 64 + c4 * 4]) = v;
            }
        }
        __syncwarp();

        // dot: 16 iters x 3 gates x 8 batch rows, f32x2
        unsigned long long a0[8], a1[8], a2[8];
#pragma unroll
        for (int b = 0; b < 8; b++) { a0[b] = 0ULL; a1[b] = 0ULL; a2[b] = 0ULL; }

#pragma unroll 4
        for (int kk = 0; kk < 16; kk++) {
            int k4 = kbase + kk * 4;
            int kl = kk * 4;
            ulonglong2 w0 = *reinterpret_cast<const ulonglong2*>(wp0 + k4);
            ulonglong2 w1 = *reinterpret_cast<const ulonglong2*>(wp1 + k4);
            ulonglong2 w2 = *reinterpret_cast<const ulonglong2*>(wp2 + k4);
#pragma unroll
            for (int b = 0; b < 8; b++) {
                ulonglong2 h2 = *reinterpret_cast<const ulonglong2*>(sh_hs + b * 64 + kl);
                fma2(a0[b], h2.x, w0.x); fma2(a0[b], h2.y, w0.y);
                fma2(a1[b], h2.x, w1.x); fma2(a1[b], h2.y, w1.y);
                fma2(a2[b], h2.x, w2.x); fma2(a2[b], h2.y, w2.y);
            }
        }

        __syncthreads();   // all dots done; sh_h region now dead

        // two-round cross-warp reduce through 3072-float buffer
        float s0 = 0.f, s1 = 0.f, s2 = 0.f;
#pragma unroll
        for (int rnd = 0; rnd < 2; rnd++) {
            if ((w >> 2) == rnd) {
                float* pw = sh_part + (w & 3) * (3 * BTILE * 32);
#pragma unroll
                for (int b = 0; b < 8; b++) {
                    pw[(0 * BTILE + b) * 32 + jg] = f32x2_sum(a0[b]);
                    pw[(1 * BTILE + b) * 32 + jg] = f32x2_sum(a1[b]);
                    pw[(2 * BTILE + b) * 32 + jg] = f32x2_sum(a2[b]);
                }
            }
            __syncthreads();
#pragma unroll
            for (int ww = 0; ww < 4; ww++) {
                const float* pw = sh_part + ww * (3 * BTILE * 32);
                s0 += pw[(0 * BTILE + w) * 32 + jg];
                s1 += pw[(1 * BTILE + w) * 32 + jg];
                s2 += pw[(2 * BTILE + w) * 32 + jg];
            }
            __syncthreads();
        }

        // gates (fast math; __expf rel err ~2^-21, well within budget)
        float hr = s0 + bh0, hz = s1 + bh1, hn = s2 + bh2;
        float r = __frcp_rn(1.f + __expf(-(xr + hr)));
        float z = __frcp_rn(1.f + __expf(-(xz + hz)));
        float te = __expf(2.f * (xn + r * hn));
        float n = (te - 1.f) * __frcp_rn(te + 1.f);
        bool m = (t < mylen);
        hnew = m ? ((1.f - z) * n + z * hprev) : hprev;
        hprev = hnew;

        hbuf[bglob * E_SZ + e] = hnew;
        __syncthreads();                     // all 8 rows of this CTA's slice stored
        if (tid == 0) ctr_release_add(my_ctr);

        ybuf[((size_t)t * B_SZ + bglob) * E_SZ + e] = m ? hnew : 0.f;
    }

    finals[bglob * E_SZ + e] = hnew;
}

// ---------------- launch (serial; overlap reverted) ----------------
extern "C" void kernel_launch(void* const* d_in, const int* in_sizes, int n_in,
                              void* d_out, int out_size) {
    const int*   input_batch = (const int*)d_in[0];
    const int*   lens        = (const int*)d_in[1];
    const float* emb         = (const float*)d_in[2];
    const float* W_ih        = (const float*)d_in[3];
    const float* W_hh        = (const float*)d_in[4];
    const float* b_ih        = (const float*)d_in[5];
    const float* b_hh        = (const float*)d_in[6];
    float* out = (float*)d_out;

    void* p;
    cudaGetSymbolAddress(&p, g_x);     float* gx  = (float*)p;
    cudaGetSymbolAddress(&p, g_xproj); float* gxp = (float*)p;
    cudaGetSymbolAddress(&p, g_h);     float* gh  = (float*)p;

    cudaFuncSetAttribute(gru_recur_kernel,
                         cudaFuncAttributeMaxDynamicSharedMemorySize, RSMEM_BYTES);

    const int M = M_ROWS;
    const size_t out_x_elems = (size_t)T_SEQ * B_SZ * E_SZ;
    float* finals0 = out + out_x_elems;
    float* finals1 = out + out_x_elems + B_SZ * E_SZ;

    {
        int total = T_SEQ * B_SZ * (E_SZ / 4);
        embed_kernel<<<(total + 255) / 256, 256>>>(input_batch, emb, gx);
    }
    gemm_nt_bias<<<dim3(G3E / BN, M / BM), 256>>>(gx, W_ih, b_ih, gxp, M, G3E, E_SZ);
    gru_recur_kernel<<<RGRID, 256, RSMEM_BYTES>>>(gxp, W_hh, b_hh, lens, gh, gx, finals0, 0);
    gemm_nt_bias<<<dim3(G3E / BN, M / BM), 256>>>(gx, W_ih + (size_t)G3E * E_SZ,
                                                  b_ih + G3E, gxp, M, G3E, E_SZ);
    gru_recur_kernel<<<RGRID, 256, RSMEM_BYTES>>>(gxp, W_hh + (size_t)G3E * E_SZ,
                                                  b_hh + G3E, lens, gh, out, finals1, 1);
}